// round 1
// baseline (speedup 1.0000x reference)
#include <cuda_runtime.h>
#include <cstdint>

// Shapes (fixed)
#define BB   8
#define SS   512
#define MEM_ 512
#define LL   4
#define EE   512
#define HH   8
#define DH_  64
#define OBS_ 128
#define KK   1024   // MEM + S

// ---------------- scratch (static device globals; no runtime alloc) ----------
__device__ float g_x [BB*SS*EE];
__device__ float g_h [BB*SS*EE];
__device__ float g_hn[BB*SS*EE];
__device__ float g_t [BB*SS*EE];
__device__ float g_vk[BB*KK*EE];
__device__ float g_q [BB*SS*EE];
__device__ float g_k [BB*KK*EE];
__device__ float g_v [BB*KK*EE];
__device__ float g_o [BB*SS*EE];
__device__ float g_r [KK*EE];
__device__ float g_pe[KK*EE];

// ---------------- positional embedding ---------------------------------------
__global__ void pe_kernel(float* __restrict__ pe) {
    int idx = blockIdx.x * 256 + threadIdx.x;          // < 1024*512
    int m = idx >> 9, c = idx & 511;
    double pos  = (double)(KK - m);                    // pos_seq = K..1
    int    t2   = c & 255;
    double invf = exp(-((double)(2 * t2) / 512.0) * log(10000.0));
    double a    = pos * invf;
    pe[idx] = (float)((c < 256) ? sin(a) : cos(a));
}

// ---------------- layer norm helpers -----------------------------------------
__device__ __forceinline__ void ln_row(const float* __restrict__ src,
                                       float* __restrict__ dst,
                                       const float* __restrict__ g,
                                       const float* __restrict__ be,
                                       int lane) {
    float4 vals[4];
    float s = 0.f, ss = 0.f;
#pragma unroll
    for (int t = 0; t < 4; t++) {
        vals[t] = *(const float4*)(src + lane * 4 + t * 128);
        s  += vals[t].x + vals[t].y + vals[t].z + vals[t].w;
        ss += vals[t].x*vals[t].x + vals[t].y*vals[t].y
            + vals[t].z*vals[t].z + vals[t].w*vals[t].w;
    }
#pragma unroll
    for (int o = 16; o; o >>= 1) {
        s  += __shfl_xor_sync(0xffffffffu, s,  o);
        ss += __shfl_xor_sync(0xffffffffu, ss, o);
    }
    float mean = s * (1.f / 512.f);
    float var  = ss * (1.f / 512.f) - mean * mean;
    float rstd = rsqrtf(var + 1e-6f);
#pragma unroll
    for (int t = 0; t < 4; t++) {
        int e = lane * 4 + t * 128;
        float4 o4;
        o4.x = (vals[t].x - mean) * rstd * g[e+0] + be[e+0];
        o4.y = (vals[t].y - mean) * rstd * g[e+1] + be[e+1];
        o4.z = (vals[t].z - mean) * rstd * g[e+2] + be[e+2];
        o4.w = (vals[t].w - mean) * rstd * g[e+3] + be[e+3];
        *(float4*)(dst + e) = o4;
    }
}

// vk = LN(concat(memories[:,:,l], x))  ->  [B, K, E]
__global__ void ln_concat_k(const float* __restrict__ mem, const float* __restrict__ x,
                            const float* __restrict__ gam, const float* __restrict__ bet,
                            float* __restrict__ out, int l) {
    int row  = blockIdx.x * 8 + (threadIdx.x >> 5);   // 0 .. B*K-1
    int lane = threadIdx.x & 31;
    int b = row >> 10, j = row & 1023;
    const float* src = (j < MEM_)
        ? (mem + ((long)(b * MEM_ + j) * LL + l) * EE)
        : (x   +  (long)(b * SS + (j - MEM_)) * EE);
    ln_row(src, out + (long)row * EE, gam + l * EE, bet + l * EE, lane);
}

__global__ void ln_plain_k(const float* __restrict__ in,
                           const float* __restrict__ gam, const float* __restrict__ bet,
                           float* __restrict__ out, int l) {
    int row  = blockIdx.x * 8 + (threadIdx.x >> 5);
    int lane = threadIdx.x & 31;
    ln_row(in + (long)row * EE, out + (long)row * EE, gam + l * EE, bet + l * EE, lane);
}

// ---------------- SGEMM: C = A@B (+bias) (+gelu | +residual) ------------------
// A: [M,Kd] with batched-row mapping arow = (m/rpb)*bstride + m%rpb
// B: [Kd,N] row-major.  MODE: 0 bias, 1 bias+gelu, 2 bias+residual, 3 nothing
template<int MODE>
__global__ __launch_bounds__(256)
void sgemm_k(const float* __restrict__ A, const float* __restrict__ B,
             const float* __restrict__ bias, const float* __restrict__ res,
             float* __restrict__ C, int M, int N, int Kd, int rpb, int bstride) {
    __shared__ __align__(16) float As[16][64];
    __shared__ __align__(16) float Bs[16][64];
    int tid = threadIdx.x;
    int tx = tid & 15, ty = tid >> 4;
    int m0 = blockIdx.y * 64, n0 = blockIdx.x * 64;
    float acc[4][4] = {};

    int aRow = tid >> 2;
    int aK   = (tid & 3) * 4;
    int gm   = m0 + aRow;
    long arow = (long)(gm / rpb) * bstride + (gm % rpb);
    const float* Aptr = A + arow * (long)Kd + aK;
    int bRow = tid >> 4;
    int bCol = (tid & 15) * 4;
    const float* Bptr = B + (long)bRow * N + n0 + bCol;

    for (int k0 = 0; k0 < Kd; k0 += 16) {
        float4 a4 = *(const float4*)(Aptr + k0);
        As[aK+0][aRow] = a4.x; As[aK+1][aRow] = a4.y;
        As[aK+2][aRow] = a4.z; As[aK+3][aRow] = a4.w;
        *(float4*)&Bs[bRow][bCol] = *(const float4*)(Bptr + (long)k0 * N);
        __syncthreads();
#pragma unroll
        for (int kk = 0; kk < 16; kk++) {
            float4 av = *(const float4*)&As[kk][ty * 4];
            float4 bv = *(const float4*)&Bs[kk][tx * 4];
            float a_[4] = {av.x, av.y, av.z, av.w};
            float b_[4] = {bv.x, bv.y, bv.z, bv.w};
#pragma unroll
            for (int i = 0; i < 4; i++)
#pragma unroll
                for (int j = 0; j < 4; j++) acc[i][j] += a_[i] * b_[j];
        }
        __syncthreads();
    }

    float4 b4 = make_float4(0.f, 0.f, 0.f, 0.f);
    if (MODE != 3) b4 = *(const float4*)(bias + n0 + tx * 4);
#pragma unroll
    for (int i = 0; i < 4; i++) {
        int m = m0 + ty * 4 + i;
        float4 o4;
        o4.x = acc[i][0] + b4.x; o4.y = acc[i][1] + b4.y;
        o4.z = acc[i][2] + b4.z; o4.w = acc[i][3] + b4.w;
        if (MODE == 1) {
            float* p = &o4.x;
#pragma unroll
            for (int j = 0; j < 4; j++) {
                float xg = p[j];
                p[j] = 0.5f * xg * (1.0f + tanhf(0.7978845608028654f *
                                                 (xg + 0.044715f * xg * xg * xg)));
            }
        }
        if (MODE == 2) {
            float4 r4 = *(const float4*)(res + (long)m * N + n0 + tx * 4);
            o4.x += r4.x; o4.y += r4.y; o4.z += r4.z; o4.w += r4.w;
        }
        *(float4*)(C + (long)m * N + n0 + tx * 4) = o4;
    }
}

// ---------------- fused rel-attention -----------------------------------------
// score(i,j) = 0.125*[(q_i+u)·k_j + (q_i+v)·r_{j+S-1-i}]  if j <= MEM+i else -1e30
// QT=16 queries per block, KT=32 keys per tile, online softmax.
__global__ __launch_bounds__(256)
void attn_k(const float* __restrict__ q, const float* __restrict__ k,
            const float* __restrict__ v, const float* __restrict__ r,
            const float* __restrict__ ub, const float* __restrict__ vb,
            float* __restrict__ o, int l) {
    int b = blockIdx.z, h = blockIdx.y, i0 = blockIdx.x * 16;
    __shared__ float qu[16][64], qv[16][64];
    __shared__ float ks[32][65], vs[32][65];
    __shared__ float rs[47][65];
    __shared__ float ps[16][33];
    int tid = threadIdx.x, w = tid >> 5, lane = tid & 31;
    const float* up = ub + (l * HH + h) * DH_;
    const float* vp = vb + (l * HH + h) * DH_;

    for (int idx = tid; idx < 16 * 64; idx += 256) {
        int qi = idx >> 6, d = idx & 63;
        float qval = q[((long)(b * SS + i0 + qi)) * EE + h * DH_ + d];
        qu[qi][d] = qval + up[d];
        qv[qi][d] = qval + vp[d];
    }

    float m_[2] = {-1e38f, -1e38f}, ls[2] = {0.f, 0.f};
    float acc[2][2] = {};
    int jmax   = MEM_ + i0 + 15;
    int ntiles = jmax / 32 + 1;
    int rb0    = SS - 16 - i0;   // rb = j0 + rb0  (>= 0 always)

    for (int t = 0; t < ntiles; t++) {
        int j0 = t * 32;
        __syncthreads();
        for (int idx = tid; idx < 32 * 64; idx += 256) {
            int kj = idx >> 6, d = idx & 63;
            long g = ((long)(b * KK + j0 + kj)) * EE + h * DH_ + d;
            ks[kj][d] = k[g];
            vs[kj][d] = v[g];
        }
        int rb = j0 + rb0;
        for (int idx = tid; idx < 47 * 64; idx += 256) {
            int rr = idx >> 6, d = idx & 63;
            int ridx = rb + rr; if (ridx > KK - 1) ridx = KK - 1;
            rs[rr][d] = r[(long)ridx * EE + h * DH_ + d];
        }
        __syncthreads();

#pragma unroll
        for (int rsub = 0; rsub < 2; rsub++) {
            int qi = w + rsub * 8;
            float s1 = 0.f, s2 = 0.f;
            int rrow = lane - qi + 15;           // in [0,46]
#pragma unroll 8
            for (int d = 0; d < 64; d++) {
                s1 += qu[qi][d] * ks[lane][d];
                s2 += qv[qi][d] * rs[rrow][d];
            }
            float sc = ((j0 + lane) <= MEM_ + i0 + qi) ? (s1 + s2) * 0.125f : -1e30f;
            float mt = sc;
#pragma unroll
            for (int off = 16; off; off >>= 1)
                mt = fmaxf(mt, __shfl_xor_sync(0xffffffffu, mt, off));
            float nm   = fmaxf(m_[rsub], mt);
            float corr = __expf(m_[rsub] - nm);
            float p    = __expf(sc - nm);
            ps[qi][lane] = p;
            float rsum = p;
#pragma unroll
            for (int off = 16; off; off >>= 1)
                rsum += __shfl_xor_sync(0xffffffffu, rsum, off);
            ls[rsub] = ls[rsub] * corr + rsum;
            m_[rsub] = nm;
            float a0 = acc[rsub][0] * corr, a1 = acc[rsub][1] * corr;
            __syncwarp();
#pragma unroll 8
            for (int kj = 0; kj < 32; kj++) {
                float pv = ps[qi][kj];
                a0 += pv * vs[kj][lane];
                a1 += pv * vs[kj][lane + 32];
            }
            acc[rsub][0] = a0; acc[rsub][1] = a1;
        }
    }

#pragma unroll
    for (int rsub = 0; rsub < 2; rsub++) {
        int qi = w + rsub * 8;
        float inv = 1.0f / ls[rsub];
        long base = ((long)(b * SS + i0 + qi)) * EE + h * DH_;
        o[base + lane]      = acc[rsub][0] * inv;
        o[base + 32 + lane] = acc[rsub][1] * inv;
    }
}

// ---------------- host orchestration ------------------------------------------
extern "C" void kernel_launch(void* const* d_in, const int* in_sizes, int n_in,
                              void* d_out, int out_size) {
    (void)in_sizes; (void)n_in; (void)out_size;
    const float* obs    = (const float*)d_in[0];
    const float* mems   = (const float*)d_in[1];
    // d_in[2] = mask (recomputed in-kernel)
    const float* W_enc  = (const float*)d_in[3];
    const float* b_enc  = (const float*)d_in[4];
    const float* ln1_s  = (const float*)d_in[5];
    const float* ln1_b  = (const float*)d_in[6];
    const float* Wq     = (const float*)d_in[7];
    const float* bq     = (const float*)d_in[8];
    const float* Wk     = (const float*)d_in[9];
    const float* bk     = (const float*)d_in[10];
    const float* Wv     = (const float*)d_in[11];
    const float* bv     = (const float*)d_in[12];
    const float* Wr     = (const float*)d_in[13];
    const float* ub     = (const float*)d_in[14];
    const float* vbias  = (const float*)d_in[15];
    const float* Wo     = (const float*)d_in[16];
    const float* bo     = (const float*)d_in[17];
    const float* ln2_s  = (const float*)d_in[18];
    const float* ln2_b  = (const float*)d_in[19];
    const float* W1     = (const float*)d_in[20];
    const float* b1     = (const float*)d_in[21];
    const float* W2     = (const float*)d_in[22];
    const float* b2     = (const float*)d_in[23];
    float* out = (float*)d_out;

    float *px, *ph, *phn, *pt, *pvk, *pq, *pk, *pv, *po, *pr, *ppe;
    cudaGetSymbolAddress((void**)&px,  g_x);
    cudaGetSymbolAddress((void**)&ph,  g_h);
    cudaGetSymbolAddress((void**)&phn, g_hn);
    cudaGetSymbolAddress((void**)&pt,  g_t);
    cudaGetSymbolAddress((void**)&pvk, g_vk);
    cudaGetSymbolAddress((void**)&pq,  g_q);
    cudaGetSymbolAddress((void**)&pk,  g_k);
    cudaGetSymbolAddress((void**)&pv,  g_v);
    cudaGetSymbolAddress((void**)&po,  g_o);
    cudaGetSymbolAddress((void**)&pr,  g_r);
    cudaGetSymbolAddress((void**)&ppe, g_pe);

    const int BIG = 1 << 30;
    const int LW  = EE * EE;      // per-layer weight stride (512*512)

    // encoder: x = obs @ W_enc + b_enc   [4096,512] = [4096,128]@[128,512]
    sgemm_k<0><<<dim3(8, 64), 256>>>(obs, W_enc, b_enc, nullptr, px,
                                     BB * SS, EE, OBS_, BIG, 0);
    pe_kernel<<<(KK * EE) / 256, 256>>>(ppe);

    for (int l = 0; l < LL; l++) {
        ln_concat_k<<<(BB * KK) / 8, 256>>>(mems, px, ln1_s, ln1_b, pvk, l);

        sgemm_k<0><<<dim3(8, 128), 256>>>(pvk, Wk + (long)l * LW, bk + l * EE,
                                          nullptr, pk, BB * KK, EE, EE, BIG, 0);
        sgemm_k<0><<<dim3(8, 128), 256>>>(pvk, Wv + (long)l * LW, bv + l * EE,
                                          nullptr, pv, BB * KK, EE, EE, BIG, 0);
        // q uses the x-rows of vk: arow = (m/S)*K + m%S, base offset MEM*E
        sgemm_k<0><<<dim3(8, 64), 256>>>(pvk + MEM_ * EE, Wq + (long)l * LW,
                                         bq + l * EE, nullptr, pq,
                                         BB * SS, EE, EE, SS, KK);
        sgemm_k<3><<<dim3(8, 16), 256>>>(ppe, Wr + (long)l * LW, nullptr, nullptr,
                                         pr, KK, EE, EE, BIG, 0);

        attn_k<<<dim3(SS / 16, HH, BB), 256>>>(pq, pk, pv, pr, ub, vbias, po, l);

        sgemm_k<2><<<dim3(8, 64), 256>>>(po, Wo + (long)l * LW, bo + l * EE,
                                         px, ph, BB * SS, EE, EE, BIG, 0);
        ln_plain_k<<<(BB * SS) / 8, 256>>>(ph, ln2_s, ln2_b, phn, l);
        sgemm_k<1><<<dim3(8, 64), 256>>>(phn, W1 + (long)l * LW, b1 + l * EE,
                                         nullptr, pt, BB * SS, EE, EE, BIG, 0);
        float* xo = (l == LL - 1) ? out : px;
        sgemm_k<2><<<dim3(8, 64), 256>>>(pt, W2 + (long)l * LW, b2 + l * EE,
                                         ph, xo, BB * SS, EE, EE, BIG, 0);
    }
}

// round 4
// speedup vs baseline: 3.2875x; 3.2875x over previous
#include <cuda_runtime.h>
#include <cstdint>

// Shapes (fixed)
#define BB   8
#define SS   512
#define MEM_ 512
#define LL   4
#define EE   512
#define HH   8
#define DH_  64
#define OBS_ 128
#define KK   1024   // MEM + S
#define LW   (EE*EE)

// ---------------- scratch (static device globals) -----------------------------
__device__ float g_x [BB*SS*EE];
__device__ float g_h [BB*SS*EE];
__device__ float g_hn[BB*SS*EE];
__device__ float g_t [BB*SS*EE];
__device__ float g_vk[BB*KK*EE];
__device__ float g_q [BB*SS*EE];
__device__ float g_k [BB*KK*EE];
__device__ float g_v [BB*KK*EE];
__device__ float g_o [BB*SS*EE];
__device__ float g_r [KK*EE];
__device__ float g_pe[KK*EE];
__device__ float g_sc[(long)BB*HH*SS*KK];   // scores / probs (in-place)
__device__ float g_P [(long)BB*HH*SS*KK];   // rel-position term

// ---------------- helpers ------------------------------------------------------
__device__ __forceinline__ uint32_t f2tf32(float x) {
    uint32_t o;
    asm("cvt.rna.tf32.f32 %0, %1;" : "=r"(o) : "f"(x));
    return o;
}
__device__ __forceinline__ void mma_tf32(float* d, const uint32_t* a, const uint32_t* b) {
    asm volatile(
        "mma.sync.aligned.m16n8k8.row.col.f32.tf32.tf32.f32 "
        "{%0,%1,%2,%3}, {%4,%5,%6,%7}, {%8,%9}, {%0,%1,%2,%3};"
        : "+f"(d[0]), "+f"(d[1]), "+f"(d[2]), "+f"(d[3])
        : "r"(a[0]), "r"(a[1]), "r"(a[2]), "r"(a[3]), "r"(b[0]), "r"(b[1]));
}
__device__ __forceinline__ float gelu_f(float x) {
    return 0.5f * x * (1.0f + tanhf(0.7978845608028654f * (x + 0.044715f * x * x * x)));
}

// ---------------- unified tf32 mma.sync GEMM -----------------------------------
// C[z][m,n] = A[z][m,:] @ B[z][:,n], tile 128(M) x 64(N), K-chunk 32, 256 thr.
// batch offset(z) = (z/Hd)*outer + (z%Hd)*inner
// BTR=false: B stored [Kd, N] row-major (weights, v) -> direct coalesced load.
// BTR=true : B stored [N, Kd] row-major (k, r)       -> transpose on load.
// AADD: A' = (A + addv[(z%Hd)*64 + kd]) * 0.125   (q+u / q+v with scale folded)
// EPI: 0 none | 1 +bias | 2 +bias+gelu | 3 +bias+residual
#define AS_STRIDE 36
#define BS_STRIDE 72
#define A_BUF (128 * AS_STRIDE)              // 4608 floats
#define B_BUF (32 * BS_STRIDE)               // 2304 floats
#define SMEM_FLOATS (2 * (A_BUF + B_BUF))    // 13824 floats = 55296 B

template<int EPI, bool BTR, bool AADD>
__global__ __launch_bounds__(256)
void mma_gemm(const float* __restrict__ A, long a_o, long a_i, int lda,
              const float* __restrict__ B, long b_o, long b_i, int ldb,
              float* __restrict__ C, long c_o, long c_i, int ldc,
              const float* __restrict__ bias, const float* __restrict__ resid,
              const float* __restrict__ addv, int Hd, int Kd) {
    extern __shared__ float smem[];
    float* sA = smem;                  // [2][128][AS_STRIDE]
    float* sB = smem + 2 * A_BUF;      // [2][32][BS_STRIDE]

    const int tid = threadIdx.x;
    const int z = blockIdx.z;
    const int m0 = blockIdx.y * 128;
    const int n0 = blockIdx.x * 64;

    const long aoff = ((long)(z / Hd)) * a_o + (long)(z % Hd) * a_i;
    const long boff = ((long)(z / Hd)) * b_o + (long)(z % Hd) * b_i;
    const long coff = ((long)(z / Hd)) * c_o + (long)(z % Hd) * c_i;
    const float* Ap = A + aoff + (long)m0 * lda;
    const float* Bp = B + boff + (BTR ? (long)n0 * ldb : (long)n0);
    const float* av = AADD ? (addv + (z % Hd) * DH_) : nullptr;

    const int lane = tid & 31, w = tid >> 5;
    const int g = lane >> 2, t4 = lane & 3;
    const int m_base = (w & 3) * 32;       // warp M offset within block
    const int n_base = (w >> 2) * 32;      // warp N offset

    float ra[16], rb[8];

    // ---- global fetch of one chunk into registers ----
    auto fetch = [&](int c) {
#pragma unroll
        for (int i = 0; i < 4; i++) {               // A: 1024 float4 slots
            int q = tid + i * 256;
            int row = q >> 3, c4 = q & 7;
            float4 v = *(const float4*)(Ap + (long)row * lda + c * 32 + c4 * 4);
            if (AADD) {
                float4 a4 = *(const float4*)(av + c * 32 + c4 * 4);
                v.x = (v.x + a4.x) * 0.125f; v.y = (v.y + a4.y) * 0.125f;
                v.z = (v.z + a4.z) * 0.125f; v.w = (v.w + a4.w) * 0.125f;
            }
            ra[i*4+0] = v.x; ra[i*4+1] = v.y; ra[i*4+2] = v.z; ra[i*4+3] = v.w;
        }
#pragma unroll
        for (int i = 0; i < 2; i++) {               // B: 512 float4 slots
            int q = tid + i * 256;
            float4 v;
            if (!BTR) {
                // B[Kd,N]: K-chunk advances along ROWS: row (c*32+row), col c4*4
                int row = q >> 4, c4 = q & 15;
                v = *(const float4*)(Bp + (long)(c * 32 + row) * ldb + c4 * 4);
            } else {
                // B[N,Kd]: row = n index, K-chunk advances along columns
                int nn = q >> 3, kc4 = q & 7;
                v = *(const float4*)(Bp + (long)nn * ldb + c * 32 + kc4 * 4);
            }
            rb[i*4+0] = v.x; rb[i*4+1] = v.y; rb[i*4+2] = v.z; rb[i*4+3] = v.w;
        }
    };
    // ---- store registers into smem buffer bf (tf32-rounded) ----
    auto stage = [&](int bf) {
        float* dA = sA + bf * A_BUF;
        float* dB = sB + bf * B_BUF;
#pragma unroll
        for (int i = 0; i < 4; i++) {
            int q = tid + i * 256;
            int row = q >> 3, c4 = q & 7;
            uint32_t* d = (uint32_t*)(dA + row * AS_STRIDE + c4 * 4);
            d[0] = f2tf32(ra[i*4+0]); d[1] = f2tf32(ra[i*4+1]);
            d[2] = f2tf32(ra[i*4+2]); d[3] = f2tf32(ra[i*4+3]);
        }
#pragma unroll
        for (int i = 0; i < 2; i++) {
            int q = tid + i * 256;
            if (!BTR) {
                int row = q >> 4, c4 = q & 15;      // row = k, c4*4 = n
                uint32_t* d = (uint32_t*)(dB + row * BS_STRIDE + c4 * 4);
                d[0] = f2tf32(rb[i*4+0]); d[1] = f2tf32(rb[i*4+1]);
                d[2] = f2tf32(rb[i*4+2]); d[3] = f2tf32(rb[i*4+3]);
            } else {
                int nn = q >> 3, kc4 = q & 7;       // transpose: [k][n]
#pragma unroll
                for (int j = 0; j < 4; j++)
                    *(uint32_t*)(dB + (kc4 * 4 + j) * BS_STRIDE + nn) = f2tf32(rb[i*4+j]);
            }
        }
    };

    float acc[2][4][4] = {};
    const int nch = Kd / 32;

    fetch(0); stage(0);
    __syncthreads();

    for (int c = 0; c < nch; c++) {
        const int bf = c & 1;
        if (c + 1 < nch) fetch(c + 1);

        const float* cA = sA + bf * A_BUF;
        const float* cB = sB + bf * B_BUF;
#pragma unroll
        for (int ks = 0; ks < 4; ks++) {
            const int k = ks * 8;
            uint32_t af[2][4], bfr[4][2];
#pragma unroll
            for (int mt = 0; mt < 2; mt++) {
                const float* p = cA + (m_base + mt * 16 + g) * AS_STRIDE + k + t4;
                af[mt][0] = __float_as_uint(p[0]);
                af[mt][1] = __float_as_uint(p[8 * AS_STRIDE]);
                af[mt][2] = __float_as_uint(p[4]);
                af[mt][3] = __float_as_uint(p[8 * AS_STRIDE + 4]);
            }
#pragma unroll
            for (int nt = 0; nt < 4; nt++) {
                const float* p = cB + (k + t4) * BS_STRIDE + n_base + nt * 8 + g;
                bfr[nt][0] = __float_as_uint(p[0]);
                bfr[nt][1] = __float_as_uint(p[4 * BS_STRIDE]);
            }
#pragma unroll
            for (int mt = 0; mt < 2; mt++)
#pragma unroll
                for (int nt = 0; nt < 4; nt++)
                    mma_tf32(acc[mt][nt], af[mt], bfr[nt]);
        }
        if (c + 1 < nch) stage((c + 1) & 1);
        __syncthreads();
    }

    // ---- epilogue ----
#pragma unroll
    for (int mt = 0; mt < 2; mt++) {
#pragma unroll
        for (int half = 0; half < 2; half++) {
            const int row = m0 + m_base + mt * 16 + g + half * 8;
            float* Cr = C + coff + (long)row * ldc + n0;
            const float* Rr = (EPI == 3) ? (resid + coff + (long)row * ldc + n0) : nullptr;
#pragma unroll
            for (int nt = 0; nt < 4; nt++) {
                const int cn = n_base + nt * 8 + t4 * 2;
                float2 o;
                o.x = acc[mt][nt][half * 2 + 0];
                o.y = acc[mt][nt][half * 2 + 1];
                if (EPI >= 1) {
                    float2 b2 = *(const float2*)(bias + n0 + cn);
                    o.x += b2.x; o.y += b2.y;
                }
                if (EPI == 2) { o.x = gelu_f(o.x); o.y = gelu_f(o.y); }
                if (EPI == 3) {
                    float2 r2 = *(const float2*)(Rr + cn);
                    o.x += r2.x; o.y += r2.y;
                }
                *(float2*)(Cr + cn) = o;
            }
        }
    }
}

// ---------------- positional embedding ----------------------------------------
__global__ void pe_kernel(float* __restrict__ pe) {
    int idx = blockIdx.x * 256 + threadIdx.x;
    int m = idx >> 9, c = idx & 511;
    double pos  = (double)(KK - m);
    int    t2   = c & 255;
    double invf = exp(-((double)(2 * t2) / 512.0) * log(10000.0));
    double a    = pos * invf;
    pe[idx] = (float)((c < 256) ? sin(a) : cos(a));
}

// ---------------- layer norm ---------------------------------------------------
__device__ __forceinline__ void ln_row(const float* __restrict__ src,
                                       float* __restrict__ dst,
                                       const float* __restrict__ g,
                                       const float* __restrict__ be, int lane) {
    float4 vals[4];
    float s = 0.f, ss = 0.f;
#pragma unroll
    for (int t = 0; t < 4; t++) {
        vals[t] = *(const float4*)(src + lane * 4 + t * 128);
        s  += vals[t].x + vals[t].y + vals[t].z + vals[t].w;
        ss += vals[t].x*vals[t].x + vals[t].y*vals[t].y
            + vals[t].z*vals[t].z + vals[t].w*vals[t].w;
    }
#pragma unroll
    for (int o = 16; o; o >>= 1) {
        s  += __shfl_xor_sync(0xffffffffu, s,  o);
        ss += __shfl_xor_sync(0xffffffffu, ss, o);
    }
    float mean = s * (1.f / 512.f);
    float var  = ss * (1.f / 512.f) - mean * mean;
    float rstd = rsqrtf(var + 1e-6f);
#pragma unroll
    for (int t = 0; t < 4; t++) {
        int e = lane * 4 + t * 128;
        float4 o4;
        o4.x = (vals[t].x - mean) * rstd * g[e+0] + be[e+0];
        o4.y = (vals[t].y - mean) * rstd * g[e+1] + be[e+1];
        o4.z = (vals[t].z - mean) * rstd * g[e+2] + be[e+2];
        o4.w = (vals[t].w - mean) * rstd * g[e+3] + be[e+3];
        *(float4*)(dst + e) = o4;
    }
}

__global__ void ln_concat_k(const float* __restrict__ mem, const float* __restrict__ x,
                            const float* __restrict__ gam, const float* __restrict__ bet,
                            float* __restrict__ out, int l) {
    int row  = blockIdx.x * 8 + (threadIdx.x >> 5);
    int lane = threadIdx.x & 31;
    int b = row >> 10, j = row & 1023;
    const float* src = (j < MEM_)
        ? (mem + ((long)(b * MEM_ + j) * LL + l) * EE)
        : (x   +  (long)(b * SS + (j - MEM_)) * EE);
    ln_row(src, out + (long)row * EE, gam + l * EE, bet + l * EE, lane);
}

__global__ void ln_plain_k(const float* __restrict__ in,
                           const float* __restrict__ gam, const float* __restrict__ bet,
                           float* __restrict__ out, int l) {
    int row  = blockIdx.x * 8 + (threadIdx.x >> 5);
    int lane = threadIdx.x & 31;
    ln_row(in + (long)row * EE, out + (long)row * EE, gam + l * EE, bet + l * EE, lane);
}

// ---------------- masked rel-shift softmax (warp per row, in-place) ------------
// row (z,i): prob[j] = softmax_j( sc[j] + P[i, j+S-1-i] ) over j<=MEM+i, else 0
__global__ __launch_bounds__(256)
void softmax_k(float* __restrict__ sc, const float* __restrict__ P) {
    long row = (long)blockIdx.x * 8 + (threadIdx.x >> 5);
    int lane = threadIdx.x & 31;
    int i = (int)(row & (SS - 1));
    int jmax = MEM_ + i;
    float* srow = sc + row * KK;
    const float* prow = P + row * KK + (SS - 1 - i);
    float v[32];
    float mx = -1e30f;
#pragma unroll
    for (int t = 0; t < 32; t++) {
        int j = t * 32 + lane;
        float x = -1e30f;
        if (j <= jmax) x = srow[j] + prow[j];
        v[t] = x;
        mx = fmaxf(mx, x);
    }
#pragma unroll
    for (int o = 16; o; o >>= 1) mx = fmaxf(mx, __shfl_xor_sync(0xffffffffu, mx, o));
    float s = 0.f;
#pragma unroll
    for (int t = 0; t < 32; t++) {
        float e = (v[t] > -1e29f) ? __expf(v[t] - mx) : 0.f;
        v[t] = e; s += e;
    }
#pragma unroll
    for (int o = 16; o; o >>= 1) s += __shfl_xor_sync(0xffffffffu, s, o);
    float inv = 1.f / s;
#pragma unroll
    for (int t = 0; t < 32; t++) srow[t * 32 + lane] = v[t] * inv;
}

// ---------------- host orchestration ------------------------------------------
#define SMEM_BYTES (SMEM_FLOATS * 4)

extern "C" void kernel_launch(void* const* d_in, const int* in_sizes, int n_in,
                              void* d_out, int out_size) {
    (void)in_sizes; (void)n_in; (void)out_size;
    const float* obs    = (const float*)d_in[0];
    const float* mems   = (const float*)d_in[1];
    const float* W_enc  = (const float*)d_in[3];
    const float* b_enc  = (const float*)d_in[4];
    const float* ln1_s  = (const float*)d_in[5];
    const float* ln1_b  = (const float*)d_in[6];
    const float* Wq     = (const float*)d_in[7];
    const float* bq     = (const float*)d_in[8];
    const float* Wk     = (const float*)d_in[9];
    const float* bk     = (const float*)d_in[10];
    const float* Wv     = (const float*)d_in[11];
    const float* bv     = (const float*)d_in[12];
    const float* Wr     = (const float*)d_in[13];
    const float* ub     = (const float*)d_in[14];
    const float* vbias  = (const float*)d_in[15];
    const float* Wo     = (const float*)d_in[16];
    const float* bo     = (const float*)d_in[17];
    const float* ln2_s  = (const float*)d_in[18];
    const float* ln2_b  = (const float*)d_in[19];
    const float* W1     = (const float*)d_in[20];
    const float* b1     = (const float*)d_in[21];
    const float* W2     = (const float*)d_in[22];
    const float* b2     = (const float*)d_in[23];
    float* out = (float*)d_out;

    float *px, *ph, *phn, *pt, *pvk, *pq, *pk, *pv_, *po, *pr, *ppe, *psc, *pP;
    cudaGetSymbolAddress((void**)&px,  g_x);
    cudaGetSymbolAddress((void**)&ph,  g_h);
    cudaGetSymbolAddress((void**)&phn, g_hn);
    cudaGetSymbolAddress((void**)&pt,  g_t);
    cudaGetSymbolAddress((void**)&pvk, g_vk);
    cudaGetSymbolAddress((void**)&pq,  g_q);
    cudaGetSymbolAddress((void**)&pk,  g_k);
    cudaGetSymbolAddress((void**)&pv_, g_v);
    cudaGetSymbolAddress((void**)&po,  g_o);
    cudaGetSymbolAddress((void**)&pr,  g_r);
    cudaGetSymbolAddress((void**)&ppe, g_pe);
    cudaGetSymbolAddress((void**)&psc, g_sc);
    cudaGetSymbolAddress((void**)&pP,  g_P);

    cudaFuncSetAttribute(mma_gemm<1,false,false>, cudaFuncAttributeMaxDynamicSharedMemorySize, SMEM_BYTES);
    cudaFuncSetAttribute(mma_gemm<0,false,false>, cudaFuncAttributeMaxDynamicSharedMemorySize, SMEM_BYTES);
    cudaFuncSetAttribute(mma_gemm<0,true ,true >, cudaFuncAttributeMaxDynamicSharedMemorySize, SMEM_BYTES);
    cudaFuncSetAttribute(mma_gemm<2,false,false>, cudaFuncAttributeMaxDynamicSharedMemorySize, SMEM_BYTES);
    cudaFuncSetAttribute(mma_gemm<3,false,false>, cudaFuncAttributeMaxDynamicSharedMemorySize, SMEM_BYTES);

    const long SE = (long)SS * EE, KE = (long)KK * EE, SK = (long)SS * KK;
    const long HSK = (long)HH * SK;

    // encoder: x = obs @ W_enc + b_enc   [4096,512] = [4096,128]@[128,512]
    mma_gemm<1,false,false><<<dim3(8, 32, 1), 256, SMEM_BYTES>>>(
        obs, 0, 0, OBS_, W_enc, 0, 0, EE, px, 0, 0, EE,
        b_enc, nullptr, nullptr, 1, OBS_);
    pe_kernel<<<(KK * EE) / 256, 256>>>(ppe);

    for (int l = 0; l < LL; l++) {
        ln_concat_k<<<(BB * KK) / 8, 256>>>(mems, px, ln1_s, ln1_b, pvk, l);

        mma_gemm<1,false,false><<<dim3(8, 64, 1), 256, SMEM_BYTES>>>(
            pvk, 0, 0, EE, Wk + (long)l * LW, 0, 0, EE, pk, 0, 0, EE,
            bk + l * EE, nullptr, nullptr, 1, EE);
        mma_gemm<1,false,false><<<dim3(8, 64, 1), 256, SMEM_BYTES>>>(
            pvk, 0, 0, EE, Wv + (long)l * LW, 0, 0, EE, pv_, 0, 0, EE,
            bv + l * EE, nullptr, nullptr, 1, EE);
        // q: rows of vk belonging to x (offset MEM*E per batch)
        mma_gemm<1,false,false><<<dim3(8, 4, BB), 256, SMEM_BYTES>>>(
            pvk + (long)MEM_ * EE, KE, 0, EE, Wq + (long)l * LW, 0, 0, EE,
            pq, SE, 0, EE, bq + l * EE, nullptr, nullptr, 1, EE);
        mma_gemm<0,false,false><<<dim3(8, 8, 1), 256, SMEM_BYTES>>>(
            ppe, 0, 0, EE, Wr + (long)l * LW, 0, 0, EE, pr, 0, 0, EE,
            nullptr, nullptr, nullptr, 1, EE);

        // AC = ((q+u)*0.125) @ k^T   [z = b*H + h]
        mma_gemm<0,true,true><<<dim3(16, 4, BB*HH), 256, SMEM_BYTES>>>(
            pq, SE, DH_, EE, pk, KE, DH_, EE, psc, HSK, SK, KK,
            nullptr, nullptr, ub + (long)l * EE, HH, DH_);
        // P = ((q+v)*0.125) @ r^T
        mma_gemm<0,true,true><<<dim3(16, 4, BB*HH), 256, SMEM_BYTES>>>(
            pq, SE, DH_, EE, pr, 0, DH_, EE, pP, HSK, SK, KK,
            nullptr, nullptr, vbias + (long)l * EE, HH, DH_);

        softmax_k<<<(BB * HH * SS) / 8, 256>>>(psc, pP);

        // o = probs @ v
        mma_gemm<0,false,false><<<dim3(1, 4, BB*HH), 256, SMEM_BYTES>>>(
            psc, HSK, SK, KK, pv_, KE, DH_, EE, po, SE, DH_, EE,
            nullptr, nullptr, nullptr, HH, KK);

        mma_gemm<3,false,false><<<dim3(8, 32, 1), 256, SMEM_BYTES>>>(
            po, 0, 0, EE, Wo + (long)l * LW, 0, 0, EE, ph, 0, 0, EE,
            bo + l * EE, px, nullptr, 1, EE);
        ln_plain_k<<<(BB * SS) / 8, 256>>>(ph, ln2_s, ln2_b, phn, l);
        mma_gemm<2,false,false><<<dim3(8, 32, 1), 256, SMEM_BYTES>>>(
            phn, 0, 0, EE, W1 + (long)l * LW, 0, 0, EE, pt, 0, 0, EE,
            b1 + l * EE, nullptr, nullptr, 1, EE);
        float* xo = (l == LL - 1) ? out : px;
        mma_gemm<3,false,false><<<dim3(8, 32, 1), 256, SMEM_BYTES>>>(
            pt, 0, 0, EE, W2 + (long)l * LW, 0, 0, EE, xo, 0, 0, EE,
            b2 + l * EE, ph, nullptr, 1, EE);
    }
}